// round 13
// baseline (speedup 1.0000x reference)
#include <cuda_runtime.h>
#include <cuda_fp16.h>
#include <math.h>
#include <stdint.h>

// Problem constants
#define ORDER   32
#define WHID    1024
#define OUTDIM  4096
#define SMAX    2048

// ---------------------------------------------------------------------------
// Scratch (device globals -- no allocations allowed)
// ---------------------------------------------------------------------------
__device__ __half g_A[SMAX * WHID];    // H1 (fp16, gemm2 input)
__device__ __half g_C[SMAX * WHID];    // H2 (fp16, gemm3 input)
__device__ __half g_W2h[WHID * WHID];
__device__ __half g_W3h[WHID * WHID];
__device__ float g_hsum[WHID];
__device__ float g_wsum[OUTDIM];
__device__ float g_bsum[1];

// ---------------------------------------------------------------------------
// PTX helpers
// ---------------------------------------------------------------------------
__device__ __forceinline__ uint32_t smem_u32(const void* p) {
    uint32_t a;
    asm("{ .reg .u64 t; cvta.to.shared.u64 t, %1; cvt.u32.u64 %0, t; }"
        : "=r"(a) : "l"(p));
    return a;
}
__device__ __forceinline__ void cp16(uint32_t saddr, const void* g) {
    asm volatile("cp.async.cg.shared.global [%0], [%1], 16;"
                 :: "r"(saddr), "l"(g) : "memory");
}
__device__ __forceinline__ void cp_commit() {
    asm volatile("cp.async.commit_group;" ::: "memory");
}
template <int N>
__device__ __forceinline__ void cp_wait() {
    asm volatile("cp.async.wait_group %0;" :: "n"(N) : "memory");
}
__device__ __forceinline__ void ldmx4(uint32_t* r, uint32_t addr) {
    asm volatile("ldmatrix.sync.aligned.m8n8.x4.shared.b16 {%0,%1,%2,%3}, [%4];"
                 : "=r"(r[0]), "=r"(r[1]), "=r"(r[2]), "=r"(r[3]) : "r"(addr));
}
__device__ __forceinline__ void mma16816h(float* d, const uint32_t* a,
                                          const uint32_t* b) {
    asm volatile(
        "mma.sync.aligned.m16n8k16.row.col.f32.f16.f16.f32 "
        "{%0,%1,%2,%3}, {%4,%5,%6,%7}, {%8,%9}, {%0,%1,%2,%3};"
        : "+f"(d[0]), "+f"(d[1]), "+f"(d[2]), "+f"(d[3])
        : "r"(a[0]), "r"(a[1]), "r"(a[2]), "r"(a[3]), "r"(b[0]), "r"(b[1]));
}

// ---------------------------------------------------------------------------
// GELU (tanh approximation, matches jax.nn.gelu)
// ---------------------------------------------------------------------------
__device__ __forceinline__ float gelu_f(float x) {
    const float k0 = 0.7978845608028654f;
    float x3 = x * x * x;
    float t = tanhf(k0 * (x + 0.044715f * x3));
    return 0.5f * x * (1.0f + t);
}

// ---------------------------------------------------------------------------
// prep: fused init + weight-convert (x8 vectorized) + layer1
//   blocks [0, 1024)      : W2/W3 -> fp16, 8 elems/thread
//   blocks [1024, 9216)   : layer1 -> g_A fp16
//   block  9216           : zero hsum + bsum
// ---------------------------------------------------------------------------
__global__ __launch_bounds__(256)
void prep_kernel(const float* __restrict__ sources,
                 const float* __restrict__ W1, const float* __restrict__ b1,
                 const float* __restrict__ W2, const float* __restrict__ W3,
                 const float* __restrict__ Wb, const float* __restrict__ bb,
                 int S) {
    const int b = blockIdx.x;
    const int tid = threadIdx.x;
    const int M1 = WHID * WHID;

    if (b < 1024) {
        int e = (b * 256 + tid) * 8;
        const float4* src;
        __half* dst;
        if (e < M1) { src = reinterpret_cast<const float4*>(W2 + e); dst = g_W2h + e; }
        else        { src = reinterpret_cast<const float4*>(W3 + (e - M1)); dst = g_W3h + (e - M1); }
        float4 f0 = src[0], f1 = src[1];
        __half h[8];
        h[0] = __float2half_rn(f0.x); h[1] = __float2half_rn(f0.y);
        h[2] = __float2half_rn(f0.z); h[3] = __float2half_rn(f0.w);
        h[4] = __float2half_rn(f1.x); h[5] = __float2half_rn(f1.y);
        h[6] = __float2half_rn(f1.z); h[7] = __float2half_rn(f1.w);
        *reinterpret_cast<uint4*>(dst) = *reinterpret_cast<uint4*>(h);
    } else if (b < 9216) {
        int idx = (b - 1024) * 256 + tid;
        int s = idx >> 10;
        int j = idx & (WHID - 1);
        float4 src = reinterpret_cast<const float4*>(sources)[s];
        float4 w   = reinterpret_cast<const float4*>(W1)[j];
        float acc = src.x * w.x + src.y * w.y + src.z * w.z + src.w * w.w + b1[j];
        g_A[idx] = __float2half_rn(gelu_f(acc));
    } else {
        for (int j = tid; j < WHID; j += 256) g_hsum[j] = 0.0f;
        float wb0 = Wb[0], wb1 = Wb[1], wb2 = Wb[2], wb3 = Wb[3];
        float acc = 0.0f;
        for (int s = tid; s < S; s += 256) {
            float4 v = reinterpret_cast<const float4*>(sources)[s];
            acc += v.x * wb0 + v.y * wb1 + v.z * wb2 + v.w * wb3;
        }
        __shared__ float red[256];
        red[tid] = acc;
        __syncthreads();
        for (int o = 128; o > 0; o >>= 1) {
            if (tid < o) red[tid] += red[tid + o];
            __syncthreads();
        }
        if (tid == 0) g_bsum[0] = red[0] + (float)S * bb[0];
    }
}

// ---------------------------------------------------------------------------
// mma.sync GEMM: C = gelu(A @ B^T + bias), fp16 x fp16 -> fp32 accum.
// CTA tile 128x128, BK=64 (four 16-k subtiles per stage), 512 threads /
// 16 warps, 3-stage cp.async pipeline (96KB DYNAMIC smem), 16 iterations.
// stage 0: out -> g_C (fp16);  stage 1: fused column sums -> g_hsum
// ---------------------------------------------------------------------------
__device__ __forceinline__ uint32_t sw32(uint32_t off) {
    return off ^ ((off >> 3) & 0x10);
}

#define G_STAGE  32768            // A (16KB) + B (16KB) per pipe stage
#define G_SMEM   (3 * G_STAGE)    // 96KB

__global__ __launch_bounds__(512, 1)
void mma_gemm(int stage, const float* __restrict__ bias) {
    extern __shared__ __align__(1024) char gsm[];

    const __half* A = stage ? g_C : g_A;
    const __half* B = stage ? g_W3h : g_W2h;

    const int tid = threadIdx.x;
    const int wid = tid >> 5;
    const int lane = tid & 31;
    const int bm = blockIdx.y * 128;
    const int bn = blockIdx.x * 128;
    const int wm = wid & 3;
    const int wn = wid >> 2;

    // --- loader: per stage, thread t loads 2 A-chunks + 2 B-chunks (32B each
    // contiguous) for row (t>>2), subtile (t&3) ---
    const int lrow = tid >> 2;
    const int lsub = tid & 3;
    const uint32_t loff0 = lsub * 4096 + sw32((uint32_t)(lrow * 32));
    const uint32_t loff1 = lsub * 4096 + sw32((uint32_t)(lrow * 32 + 16));
    const int gk = lsub * 16;
    const __half* srcA = A + (size_t)(bm + lrow) * WHID + gk;
    const __half* srcB = B + (size_t)(bn + lrow) * WHID + gk;

    uint32_t offA[2], offB[2];
#pragma unroll
    for (int i = 0; i < 2; i++) {
        int row = wm * 32 + i * 16 + (lane & 15);
        offA[i] = sw32((uint32_t)(row * 32 + (lane >> 4) * 16));
    }
#pragma unroll
    for (int j = 0; j < 2; j++) {
        int row = wn * 32 + j * 16 + (lane & 15);
        offB[j] = sw32((uint32_t)(row * 32 + (lane >> 4) * 16));
    }

    float acc[2][4][4];
#pragma unroll
    for (int i = 0; i < 2; i++)
#pragma unroll
        for (int j = 0; j < 4; j++)
#pragma unroll
            for (int q = 0; q < 4; q++) acc[i][j][q] = 0.0f;

    const uint32_t sbase = smem_u32(gsm);

#pragma unroll
    for (int p = 0; p < 2; p++) {
        uint32_t st = sbase + p * G_STAGE;
        cp16(st + loff0, srcA + p * 64);
        cp16(st + loff1, srcA + p * 64 + 8);
        cp16(st + 16384 + loff0, srcB + p * 64);
        cp16(st + 16384 + loff1, srcB + p * 64 + 8);
        cp_commit();
    }

    const int NIT = WHID / 64;   // 16
    for (int it = 0; it < NIT; it++) {
        const uint32_t stb = sbase + (it % 3) * G_STAGE;
        cp_wait<1>();
        __syncthreads();

        if (it + 2 < NIT) {
            uint32_t ns = sbase + ((it + 2) % 3) * G_STAGE;
            int nk = (it + 2) * 64;
            cp16(ns + loff0, srcA + nk);
            cp16(ns + loff1, srcA + nk + 8);
            cp16(ns + 16384 + loff0, srcB + nk);
            cp16(ns + 16384 + loff1, srcB + nk + 8);
        }
        cp_commit();

#pragma unroll
        for (int s = 0; s < 4; s++) {
            uint32_t ab = stb + s * 4096;
            uint32_t bb = stb + 16384 + s * 4096;
            uint32_t a[2][4], b[2][4];
#pragma unroll
            for (int i = 0; i < 2; i++) ldmx4(a[i], ab + offA[i]);
#pragma unroll
            for (int j = 0; j < 2; j++) ldmx4(b[j], bb + offB[j]);

#pragma unroll
            for (int i = 0; i < 2; i++) {
#pragma unroll
                for (int jj = 0; jj < 4; jj++) {
                    uint32_t breg[2] = { b[jj >> 1][jj & 1], b[jj >> 1][(jj & 1) + 2] };
                    mma16816h(acc[i][jj], a[i], breg);
                }
            }
        }
    }

    // --- epilogue ---
    if (stage == 0) {
#pragma unroll
        for (int i = 0; i < 2; i++) {
            int r0 = bm + wm * 32 + i * 16 + (lane >> 2);
            int r1 = r0 + 8;
#pragma unroll
            for (int jj = 0; jj < 4; jj++) {
                int col = bn + wn * 32 + jj * 8 + (lane & 3) * 2;
                float b0 = bias[col], b1 = bias[col + 1];
                __half h0 = __float2half_rn(gelu_f(acc[i][jj][0] + b0));
                __half h1 = __float2half_rn(gelu_f(acc[i][jj][1] + b1));
                *reinterpret_cast<__half2*>(g_C + (size_t)r0 * WHID + col) =
                    __half2(h0, h1);
                h0 = __float2half_rn(gelu_f(acc[i][jj][2] + b0));
                h1 = __float2half_rn(gelu_f(acc[i][jj][3] + b1));
                *reinterpret_cast<__half2*>(g_C + (size_t)r1 * WHID + col) =
                    __half2(h0, h1);
            }
        }
    } else {
        float colacc[4][2];
#pragma unroll
        for (int jj = 0; jj < 4; jj++) { colacc[jj][0] = 0.0f; colacc[jj][1] = 0.0f; }

#pragma unroll
        for (int i = 0; i < 2; i++) {
#pragma unroll
            for (int jj = 0; jj < 4; jj++) {
                int col = bn + wn * 32 + jj * 8 + (lane & 3) * 2;
                float b0 = bias[col], b1 = bias[col + 1];
                colacc[jj][0] += gelu_f(acc[i][jj][0] + b0) + gelu_f(acc[i][jj][2] + b0);
                colacc[jj][1] += gelu_f(acc[i][jj][1] + b1) + gelu_f(acc[i][jj][3] + b1);
            }
        }
#pragma unroll
        for (int o = 16; o >= 4; o >>= 1) {
#pragma unroll
            for (int jj = 0; jj < 4; jj++) {
                colacc[jj][0] += __shfl_xor_sync(0xffffffffu, colacc[jj][0], o);
                colacc[jj][1] += __shfl_xor_sync(0xffffffffu, colacc[jj][1], o);
            }
        }
        if (lane < 4) {
#pragma unroll
            for (int jj = 0; jj < 4; jj++) {
                int col = bn + wn * 32 + jj * 8 + lane * 2;
                atomicAdd(&g_hsum[col],     colacc[jj][0]);
                atomicAdd(&g_hsum[col + 1], colacc[jj][1]);
            }
        }
    }
}

// ---------------------------------------------------------------------------
// wsum: 2 rows per warp (16 outstanding float4 loads/lane -> MLP~16)
// ---------------------------------------------------------------------------
__global__ __launch_bounds__(256)
void wsum_kernel(const float* __restrict__ W4,
                 const float* __restrict__ b4, float Sf) {
    int k0 = (blockIdx.x * 8 + (threadIdx.x >> 5)) * 2;
    int lane = threadIdx.x & 31;
    const float4* row0 = reinterpret_cast<const float4*>(W4 + (size_t)k0 * WHID);
    const float4* row1 = reinterpret_cast<const float4*>(W4 + (size_t)(k0 + 1) * WHID);
    const float4* hs   = reinterpret_cast<const float4*>(g_hsum);

    float4 w0[8], w1[8], h[8];
#pragma unroll
    for (int q = 0; q < 8; q++) w0[q] = row0[lane + q * 32];
#pragma unroll
    for (int q = 0; q < 8; q++) w1[q] = row1[lane + q * 32];
#pragma unroll
    for (int q = 0; q < 8; q++) h[q] = hs[lane + q * 32];

    float a0 = 0.0f, a1 = 0.0f;
#pragma unroll
    for (int q = 0; q < 8; q++) {
        a0 += w0[q].x * h[q].x + w0[q].y * h[q].y +
              w0[q].z * h[q].z + w0[q].w * h[q].w;
        a1 += w1[q].x * h[q].x + w1[q].y * h[q].y +
              w1[q].z * h[q].z + w1[q].w * h[q].w;
    }
#pragma unroll
    for (int o = 16; o > 0; o >>= 1) {
        a0 += __shfl_xor_sync(0xffffffffu, a0, o);
        a1 += __shfl_xor_sync(0xffffffffu, a1, o);
    }
    if (lane == 0) {
        g_wsum[k0]     = a0 + Sf * b4[k0];
        g_wsum[k0 + 1] = a1 + Sf * b4[k0 + 1];
    }
}

// ---------------------------------------------------------------------------
// Fourier via tensor cores (see R12 notes).
// ---------------------------------------------------------------------------
#define F_OFF_K   0
#define F_OFF_V   16384
#define F_OFF_U   49152
#define F_OFF_OUT 115712
#define F_SMEM    116768

__global__ __launch_bounds__(256, 1)
void fourier_kernel(const float* __restrict__ r, float* __restrict__ out, int N) {
    extern __shared__ __align__(16) char fs[];
    const uint32_t sbase = smem_u32(fs);
    float* Uf = reinterpret_cast<float*>(fs + F_OFF_U);
    float* outb = reinterpret_cast<float*>(fs + F_OFF_OUT);

    const int tid = threadIdx.x;
    const int wid = tid >> 5;
    const int lane = tid & 31;
    const int wm = wid & 3;
    const int wn = wid >> 2;

    outb[tid] = 0.0f;

    for (int t = tid; t < 4096; t += 256) {
        int a = t >> 6, b = t & 63;
        int i = a & 31, j = b & 31;
        int c = (a < 32) ? ((b < 32) ? 0 : 2) : ((b < 32) ? 3 : 1);
        float w = g_wsum[c * 1024 + i * 32 + j];
        __half hi = __float2half_rn(w);
        __half lo = __float2half_rn(w - __half2float(hi));
        int ks = b >> 4;
        int b16 = b & 15;
        uint32_t off = ks * 2048 + sw32((uint32_t)(a * 32 + (b16 >> 3) * 16)) +
                       (b16 & 7) * 2;
        *reinterpret_cast<__half*>(fs + F_OFF_K + off) = hi;
        *reinterpret_cast<__half*>(fs + F_OFF_K + 8192 + off) = lo;
    }

    {
        int n = blockIdx.x * 256 + tid;
        float x = 0.0f, y = 0.0f;
        if (n < N) { x = r[2 * n + 0]; y = r[2 * n + 1]; }
        const float w1 = 0.6283185307179586f;   // 2*pi/10

        float sx1, cx1, sy1, cy1;
        sincosf(w1 * x, &sx1, &cx1);
        sincosf(w1 * y, &sy1, &cy1);

        float v[64], u[64];
        {
            float cc = cy1, ss = sy1;
            v[0] = cc; v[32] = ss;
#pragma unroll
            for (int k = 1; k < 32; k++) {
                float cn = cc * cy1 - ss * sy1;
                float sn = ss * cy1 + cc * sy1;
                cc = cn; ss = sn;
                v[k] = cc; v[32 + k] = ss;
            }
        }
        {
            float cc = cx1, ss = sx1;
            u[0] = cc; u[32] = ss;
#pragma unroll
            for (int k = 1; k < 32; k++) {
                float cn = cc * cx1 - ss * sx1;
                float sn = ss * cx1 + cc * sx1;
                cc = cn; ss = sn;
                u[k] = cc; u[32 + k] = ss;
            }
        }

#pragma unroll
        for (int ks = 0; ks < 4; ks++) {
#pragma unroll
            for (int c16 = 0; c16 < 2; c16++) {
                __half hv[8];
#pragma unroll
                for (int e = 0; e < 8; e++)
                    hv[e] = __float2half_rn(v[ks * 16 + c16 * 8 + e]);
                uint32_t off = F_OFF_V + ks * 8192 +
                               sw32((uint32_t)(tid * 32 + c16 * 16));
                *reinterpret_cast<uint4*>(fs + off) =
                    *reinterpret_cast<uint4*>(hv);
            }
        }
#pragma unroll
        for (int a = 0; a < 64; a++) Uf[a * 260 + tid] = u[a];
    }
    __syncthreads();

    const uint32_t offA = sw32((uint32_t)((wm * 16 + (lane & 15)) * 32 +
                                          (lane >> 4) * 16));
    uint32_t offB[8];
#pragma unroll
    for (int p = 0; p < 8; p++) {
        int row = wn * 128 + p * 16 + (lane & 15);
        offB[p] = sw32((uint32_t)(row * 32 + (lane >> 4) * 16));
    }

    float acc[16][4];
#pragma unroll
    for (int nt = 0; nt < 16; nt++)
#pragma unroll
        for (int q = 0; q < 4; q++) acc[nt][q] = 0.0f;

#pragma unroll
    for (int ks = 0; ks < 4; ks++) {
        uint32_t ah[4], al[4];
        ldmx4(ah, sbase + F_OFF_K + ks * 2048 + offA);
        ldmx4(al, sbase + F_OFF_K + 8192 + ks * 2048 + offA);
#pragma unroll
        for (int p = 0; p < 8; p++) {
            uint32_t bf[4];
            ldmx4(bf, sbase + F_OFF_V + ks * 8192 + offB[p]);
#pragma unroll
            for (int h = 0; h < 2; h++) {
                uint32_t breg[2] = { bf[h], bf[h + 2] };
                mma16816h(acc[p * 2 + h], ah, breg);
                mma16816h(acc[p * 2 + h], al, breg);
            }
        }
    }

    {
        int r0 = wm * 16 + (lane >> 2);
        int r1 = r0 + 8;
#pragma unroll
        for (int nt = 0; nt < 16; nt++) {
            int c0 = wn * 128 + nt * 8 + (lane & 3) * 2;
            float p0 = acc[nt][0] * Uf[r0 * 260 + c0] +
                       acc[nt][2] * Uf[r1 * 260 + c0];
            float p1 = acc[nt][1] * Uf[r0 * 260 + c0 + 1] +
                       acc[nt][3] * Uf[r1 * 260 + c0 + 1];
            p0 += __shfl_xor_sync(0xffffffffu, p0, 16);
            p1 += __shfl_xor_sync(0xffffffffu, p1, 16);
            p0 += __shfl_xor_sync(0xffffffffu, p0, 8);
            p1 += __shfl_xor_sync(0xffffffffu, p1, 8);
            p0 += __shfl_xor_sync(0xffffffffu, p0, 4);
            p1 += __shfl_xor_sync(0xffffffffu, p1, 4);
            if (lane < 4) {
                atomicAdd(&outb[c0], p0);
                atomicAdd(&outb[c0 + 1], p1);
            }
        }
    }
    __syncthreads();

    int n = blockIdx.x * 256 + tid;
    if (n < N) out[n] = g_bsum[0] + outb[tid];
}

// ---------------------------------------------------------------------------
// kernel_launch
// ---------------------------------------------------------------------------
extern "C" void kernel_launch(void* const* d_in, const int* in_sizes, int n_in,
                              void* d_out, int out_size) {
    const float* sources = (const float*)d_in[0];
    const float* r       = (const float*)d_in[1];
    const float* W1      = (const float*)d_in[2];
    const float* b1      = (const float*)d_in[3];
    const float* W2      = (const float*)d_in[4];
    const float* b2      = (const float*)d_in[5];
    const float* W3      = (const float*)d_in[6];
    const float* b3      = (const float*)d_in[7];
    const float* W4      = (const float*)d_in[8];
    const float* b4      = (const float*)d_in[9];
    const float* Wb      = (const float*)d_in[10];
    const float* bb      = (const float*)d_in[11];
    float* out = (float*)d_out;

    const int S = in_sizes[0] / 4;
    const int N = in_sizes[1] / 2;

    // allow >48KB dynamic smem (idempotent host calls; capture-safe)
    cudaFuncSetAttribute(mma_gemm,
                         cudaFuncAttributeMaxDynamicSharedMemorySize, G_SMEM);
    cudaFuncSetAttribute(fourier_kernel,
                         cudaFuncAttributeMaxDynamicSharedMemorySize, F_SMEM);

    // 1) fused prep: weight fp16 convert + layer1 + init
    prep_kernel<<<9217, 256>>>(sources, W1, b1, W2, W3, Wb, bb, S);

    // 2) tensor-core GELU-GEMMs (layers 2 and 3; layer-3 fuses column sum)
    {
        dim3 grid(WHID / 128, S / 128);
        mma_gemm<<<grid, 512, G_SMEM>>>(0, b2);   // H1 -> H2 (fp16)
        mma_gemm<<<grid, 512, G_SMEM>>>(1, b3);   // H2 -> hsum
    }

    // 3) wsum = hsum @ W4^T + S*b4
    wsum_kernel<<<OUTDIM / 16, 256>>>(W4, b4, (float)S);

    // 4) fourier expansion (tensor-core bilinear form)
    fourier_kernel<<<(N + 255) / 256, 256, F_SMEM>>>(r, out, N);
}

// round 14
// speedup vs baseline: 1.2138x; 1.2138x over previous
#include <cuda_runtime.h>
#include <cuda_fp16.h>
#include <math.h>
#include <stdint.h>

// Problem constants
#define ORDER   32
#define WHID    1024
#define OUTDIM  4096
#define SMAX    2048

// ---------------------------------------------------------------------------
// Scratch (device globals -- no allocations allowed)
// ---------------------------------------------------------------------------
__device__ __half g_A[SMAX * WHID];    // H1 (fp16, gemm2 input)
__device__ __half g_C[SMAX * WHID];    // H2 (fp16, gemm3 input)
__device__ __half g_W2h[WHID * WHID];
__device__ __half g_W3h[WHID * WHID];
__device__ float g_hsum[WHID];
__device__ float g_wsum[OUTDIM];
__device__ float g_bsum[1];

// ---------------------------------------------------------------------------
// PTX helpers
// ---------------------------------------------------------------------------
__device__ __forceinline__ uint32_t smem_u32(const void* p) {
    uint32_t a;
    asm("{ .reg .u64 t; cvta.to.shared.u64 t, %1; cvt.u32.u64 %0, t; }"
        : "=r"(a) : "l"(p));
    return a;
}
__device__ __forceinline__ void cp16(uint32_t saddr, const void* g) {
    asm volatile("cp.async.cg.shared.global [%0], [%1], 16;"
                 :: "r"(saddr), "l"(g) : "memory");
}
__device__ __forceinline__ void cp_commit() {
    asm volatile("cp.async.commit_group;" ::: "memory");
}
template <int N>
__device__ __forceinline__ void cp_wait() {
    asm volatile("cp.async.wait_group %0;" :: "n"(N) : "memory");
}
__device__ __forceinline__ void ldmx4(uint32_t* r, uint32_t addr) {
    asm volatile("ldmatrix.sync.aligned.m8n8.x4.shared.b16 {%0,%1,%2,%3}, [%4];"
                 : "=r"(r[0]), "=r"(r[1]), "=r"(r[2]), "=r"(r[3]) : "r"(addr));
}
__device__ __forceinline__ void mma16816h(float* d, const uint32_t* a,
                                          const uint32_t* b) {
    asm volatile(
        "mma.sync.aligned.m16n8k16.row.col.f32.f16.f16.f32 "
        "{%0,%1,%2,%3}, {%4,%5,%6,%7}, {%8,%9}, {%0,%1,%2,%3};"
        : "+f"(d[0]), "+f"(d[1]), "+f"(d[2]), "+f"(d[3])
        : "r"(a[0]), "r"(a[1]), "r"(a[2]), "r"(a[3]), "r"(b[0]), "r"(b[1]));
}

// ---------------------------------------------------------------------------
// GELU (tanh approximation, matches jax.nn.gelu)
// ---------------------------------------------------------------------------
__device__ __forceinline__ float gelu_f(float x) {
    const float k0 = 0.7978845608028654f;
    float x3 = x * x * x;
    float t = tanhf(k0 * (x + 0.044715f * x3));
    return 0.5f * x * (1.0f + t);
}

// ---------------------------------------------------------------------------
// prep: fused init + weight-convert (x8 vectorized) + layer1
//   blocks [0, 1024)      : W2/W3 -> fp16, 8 elems/thread
//   blocks [1024, 9216)   : layer1 -> g_A fp16
//   block  9216           : zero hsum + bsum
// ---------------------------------------------------------------------------
__global__ __launch_bounds__(256)
void prep_kernel(const float* __restrict__ sources,
                 const float* __restrict__ W1, const float* __restrict__ b1,
                 const float* __restrict__ W2, const float* __restrict__ W3,
                 const float* __restrict__ Wb, const float* __restrict__ bb,
                 int S) {
    const int b = blockIdx.x;
    const int tid = threadIdx.x;
    const int M1 = WHID * WHID;

    if (b < 1024) {
        int e = (b * 256 + tid) * 8;
        const float4* src;
        __half* dst;
        if (e < M1) { src = reinterpret_cast<const float4*>(W2 + e); dst = g_W2h + e; }
        else        { src = reinterpret_cast<const float4*>(W3 + (e - M1)); dst = g_W3h + (e - M1); }
        float4 f0 = src[0], f1 = src[1];
        __half h[8];
        h[0] = __float2half_rn(f0.x); h[1] = __float2half_rn(f0.y);
        h[2] = __float2half_rn(f0.z); h[3] = __float2half_rn(f0.w);
        h[4] = __float2half_rn(f1.x); h[5] = __float2half_rn(f1.y);
        h[6] = __float2half_rn(f1.z); h[7] = __float2half_rn(f1.w);
        *reinterpret_cast<uint4*>(dst) = *reinterpret_cast<uint4*>(h);
    } else if (b < 9216) {
        int idx = (b - 1024) * 256 + tid;
        int s = idx >> 10;
        int j = idx & (WHID - 1);
        float4 src = reinterpret_cast<const float4*>(sources)[s];
        float4 w   = reinterpret_cast<const float4*>(W1)[j];
        float acc = src.x * w.x + src.y * w.y + src.z * w.z + src.w * w.w + b1[j];
        g_A[idx] = __float2half_rn(gelu_f(acc));
    } else {
        for (int j = tid; j < WHID; j += 256) g_hsum[j] = 0.0f;
        float wb0 = Wb[0], wb1 = Wb[1], wb2 = Wb[2], wb3 = Wb[3];
        float acc = 0.0f;
        for (int s = tid; s < S; s += 256) {
            float4 v = reinterpret_cast<const float4*>(sources)[s];
            acc += v.x * wb0 + v.y * wb1 + v.z * wb2 + v.w * wb3;
        }
        __shared__ float red[256];
        red[tid] = acc;
        __syncthreads();
        for (int o = 128; o > 0; o >>= 1) {
            if (tid < o) red[tid] += red[tid + o];
            __syncthreads();
        }
        if (tid == 0) g_bsum[0] = red[0] + (float)S * bb[0];
    }
}

// ---------------------------------------------------------------------------
// mma.sync GEMM: C = gelu(A @ B^T + bias), fp16 x fp16 -> fp32 accum.
// CTA tile 128x128, BK=32, 512 threads / 16 warps, 3-stage cp.async pipeline
// (48KB static smem). PROVEN R12 configuration.
// stage 0: out -> g_C (fp16);  stage 1: fused column sums -> g_hsum
// ---------------------------------------------------------------------------
__device__ __forceinline__ uint32_t sw32(uint32_t off) {
    return off ^ ((off >> 3) & 0x10);
}

__global__ __launch_bounds__(512, 1)
void mma_gemm(int stage, const float* __restrict__ bias) {
    __shared__ __align__(1024) char smem[3][2][8192];

    const __half* A = stage ? g_C : g_A;
    const __half* B = stage ? g_W3h : g_W2h;

    const int tid = threadIdx.x;
    const int wid = tid >> 5;
    const int lane = tid & 31;
    const int bm = blockIdx.y * 128;
    const int bn = blockIdx.x * 128;
    const int wm = wid & 3;
    const int wn = wid >> 2;

    const int lrow = tid >> 2;
    const int lsub = (tid >> 1) & 1;
    const int lc16 = tid & 1;
    const uint32_t loff = lsub * 4096 + sw32((uint32_t)(lrow * 32 + lc16 * 16));
    const int gk = lsub * 16 + lc16 * 8;
    const __half* srcA = A + (size_t)(bm + lrow) * WHID + gk;
    const __half* srcB = B + (size_t)(bn + lrow) * WHID + gk;

    uint32_t offA[2], offB[2];
#pragma unroll
    for (int i = 0; i < 2; i++) {
        int row = wm * 32 + i * 16 + (lane & 15);
        offA[i] = sw32((uint32_t)(row * 32 + (lane >> 4) * 16));
    }
#pragma unroll
    for (int j = 0; j < 2; j++) {
        int row = wn * 32 + j * 16 + (lane & 15);
        offB[j] = sw32((uint32_t)(row * 32 + (lane >> 4) * 16));
    }

    float acc[2][4][4];
#pragma unroll
    for (int i = 0; i < 2; i++)
#pragma unroll
        for (int j = 0; j < 4; j++)
#pragma unroll
            for (int q = 0; q < 4; q++) acc[i][j][q] = 0.0f;

#pragma unroll
    for (int p = 0; p < 2; p++) {
        cp16(smem_u32(&smem[p][0][0]) + loff, srcA + p * 32);
        cp16(smem_u32(&smem[p][1][0]) + loff, srcB + p * 32);
        cp_commit();
    }

    const int NIT = WHID / 32;   // 32
    for (int it = 0; it < NIT; it++) {
        const int st = it % 3;
        cp_wait<1>();
        __syncthreads();

        if (it + 2 < NIT) {
            const int ns = (it + 2) % 3;
            cp16(smem_u32(&smem[ns][0][0]) + loff, srcA + (it + 2) * 32);
            cp16(smem_u32(&smem[ns][1][0]) + loff, srcB + (it + 2) * 32);
        }
        cp_commit();

#pragma unroll
        for (int s = 0; s < 2; s++) {
            uint32_t ab = smem_u32(&smem[st][0][0]) + s * 4096;
            uint32_t bb = smem_u32(&smem[st][1][0]) + s * 4096;
            uint32_t a[2][4], b[2][4];
#pragma unroll
            for (int i = 0; i < 2; i++) ldmx4(a[i], ab + offA[i]);
#pragma unroll
            for (int j = 0; j < 2; j++) ldmx4(b[j], bb + offB[j]);

#pragma unroll
            for (int i = 0; i < 2; i++) {
#pragma unroll
                for (int jj = 0; jj < 4; jj++) {
                    uint32_t breg[2] = { b[jj >> 1][jj & 1], b[jj >> 1][(jj & 1) + 2] };
                    mma16816h(acc[i][jj], a[i], breg);
                }
            }
        }
    }

    // --- epilogue ---
    if (stage == 0) {
#pragma unroll
        for (int i = 0; i < 2; i++) {
            int r0 = bm + wm * 32 + i * 16 + (lane >> 2);
            int r1 = r0 + 8;
#pragma unroll
            for (int jj = 0; jj < 4; jj++) {
                int col = bn + wn * 32 + jj * 8 + (lane & 3) * 2;
                float b0 = bias[col], b1 = bias[col + 1];
                __half h0 = __float2half_rn(gelu_f(acc[i][jj][0] + b0));
                __half h1 = __float2half_rn(gelu_f(acc[i][jj][1] + b1));
                *reinterpret_cast<__half2*>(g_C + (size_t)r0 * WHID + col) =
                    __half2(h0, h1);
                h0 = __float2half_rn(gelu_f(acc[i][jj][2] + b0));
                h1 = __float2half_rn(gelu_f(acc[i][jj][3] + b1));
                *reinterpret_cast<__half2*>(g_C + (size_t)r1 * WHID + col) =
                    __half2(h0, h1);
            }
        }
    } else {
        float colacc[4][2];
#pragma unroll
        for (int jj = 0; jj < 4; jj++) { colacc[jj][0] = 0.0f; colacc[jj][1] = 0.0f; }

#pragma unroll
        for (int i = 0; i < 2; i++) {
#pragma unroll
            for (int jj = 0; jj < 4; jj++) {
                int col = bn + wn * 32 + jj * 8 + (lane & 3) * 2;
                float b0 = bias[col], b1 = bias[col + 1];
                colacc[jj][0] += gelu_f(acc[i][jj][0] + b0) + gelu_f(acc[i][jj][2] + b0);
                colacc[jj][1] += gelu_f(acc[i][jj][1] + b1) + gelu_f(acc[i][jj][3] + b1);
            }
        }
#pragma unroll
        for (int o = 16; o >= 4; o >>= 1) {
#pragma unroll
            for (int jj = 0; jj < 4; jj++) {
                colacc[jj][0] += __shfl_xor_sync(0xffffffffu, colacc[jj][0], o);
                colacc[jj][1] += __shfl_xor_sync(0xffffffffu, colacc[jj][1], o);
            }
        }
        if (lane < 4) {
#pragma unroll
            for (int jj = 0; jj < 4; jj++) {
                int col = bn + wn * 32 + jj * 8 + lane * 2;
                atomicAdd(&g_hsum[col],     colacc[jj][0]);
                atomicAdd(&g_hsum[col + 1], colacc[jj][1]);
            }
        }
    }
}

// ---------------------------------------------------------------------------
// wsum[k] = hsum . W4[k,:] + S*b4[k]  (PROVEN R12 form: 1 row/warp, MLP~8)
// ---------------------------------------------------------------------------
__global__ __launch_bounds__(256)
void wsum_kernel(const float* __restrict__ W4,
                 const float* __restrict__ b4, float Sf) {
    int k = blockIdx.x * 8 + (threadIdx.x >> 5);
    int lane = threadIdx.x & 31;
    const float4* row = reinterpret_cast<const float4*>(W4 + (size_t)k * WHID);
    const float4* hs  = reinterpret_cast<const float4*>(g_hsum);

    float4 w[8], h[8];
#pragma unroll
    for (int q = 0; q < 8; q++) w[q] = row[lane + q * 32];
#pragma unroll
    for (int q = 0; q < 8; q++) h[q] = hs[lane + q * 32];

    float acc = 0.0f;
#pragma unroll
    for (int q = 0; q < 8; q++) {
        acc += w[q].x * h[q].x + w[q].y * h[q].y +
               w[q].z * h[q].z + w[q].w * h[q].w;
    }
#pragma unroll
    for (int o = 16; o > 0; o >>= 1) acc += __shfl_xor_sync(0xffffffffu, acc, o);
    if (lane == 0) g_wsum[k] = acc + Sf * b4[k];
}

// ---------------------------------------------------------------------------
// Fourier via tensor cores (PROVEN R12 form).
// ---------------------------------------------------------------------------
#define F_OFF_K   0
#define F_OFF_V   16384
#define F_OFF_U   49152
#define F_OFF_OUT 115712
#define F_SMEM    116768

__global__ __launch_bounds__(256, 1)
void fourier_kernel(const float* __restrict__ r, float* __restrict__ out, int N) {
    extern __shared__ __align__(16) char fs[];
    const uint32_t sbase = smem_u32(fs);
    float* Uf = reinterpret_cast<float*>(fs + F_OFF_U);
    float* outb = reinterpret_cast<float*>(fs + F_OFF_OUT);

    const int tid = threadIdx.x;
    const int wid = tid >> 5;
    const int lane = tid & 31;
    const int wm = wid & 3;
    const int wn = wid >> 2;

    outb[tid] = 0.0f;

    for (int t = tid; t < 4096; t += 256) {
        int a = t >> 6, b = t & 63;
        int i = a & 31, j = b & 31;
        int c = (a < 32) ? ((b < 32) ? 0 : 2) : ((b < 32) ? 3 : 1);
        float w = g_wsum[c * 1024 + i * 32 + j];
        __half hi = __float2half_rn(w);
        __half lo = __float2half_rn(w - __half2float(hi));
        int ks = b >> 4;
        int b16 = b & 15;
        uint32_t off = ks * 2048 + sw32((uint32_t)(a * 32 + (b16 >> 3) * 16)) +
                       (b16 & 7) * 2;
        *reinterpret_cast<__half*>(fs + F_OFF_K + off) = hi;
        *reinterpret_cast<__half*>(fs + F_OFF_K + 8192 + off) = lo;
    }

    {
        int n = blockIdx.x * 256 + tid;
        float x = 0.0f, y = 0.0f;
        if (n < N) { x = r[2 * n + 0]; y = r[2 * n + 1]; }
        const float w1 = 0.6283185307179586f;   // 2*pi/10

        float sx1, cx1, sy1, cy1;
        sincosf(w1 * x, &sx1, &cx1);
        sincosf(w1 * y, &sy1, &cy1);

        float v[64], u[64];
        {
            float cc = cy1, ss = sy1;
            v[0] = cc; v[32] = ss;
#pragma unroll
            for (int k = 1; k < 32; k++) {
                float cn = cc * cy1 - ss * sy1;
                float sn = ss * cy1 + cc * sy1;
                cc = cn; ss = sn;
                v[k] = cc; v[32 + k] = ss;
            }
        }
        {
            float cc = cx1, ss = sx1;
            u[0] = cc; u[32] = ss;
#pragma unroll
            for (int k = 1; k < 32; k++) {
                float cn = cc * cx1 - ss * sx1;
                float sn = ss * cx1 + cc * sx1;
                cc = cn; ss = sn;
                u[k] = cc; u[32 + k] = ss;
            }
        }

#pragma unroll
        for (int ks = 0; ks < 4; ks++) {
#pragma unroll
            for (int c16 = 0; c16 < 2; c16++) {
                __half hv[8];
#pragma unroll
                for (int e = 0; e < 8; e++)
                    hv[e] = __float2half_rn(v[ks * 16 + c16 * 8 + e]);
                uint32_t off = F_OFF_V + ks * 8192 +
                               sw32((uint32_t)(tid * 32 + c16 * 16));
                *reinterpret_cast<uint4*>(fs + off) =
                    *reinterpret_cast<uint4*>(hv);
            }
        }
#pragma unroll
        for (int a = 0; a < 64; a++) Uf[a * 260 + tid] = u[a];
    }
    __syncthreads();

    const uint32_t offA = sw32((uint32_t)((wm * 16 + (lane & 15)) * 32 +
                                          (lane >> 4) * 16));
    uint32_t offB[8];
#pragma unroll
    for (int p = 0; p < 8; p++) {
        int row = wn * 128 + p * 16 + (lane & 15);
        offB[p] = sw32((uint32_t)(row * 32 + (lane >> 4) * 16));
    }

    float acc[16][4];
#pragma unroll
    for (int nt = 0; nt < 16; nt++)
#pragma unroll
        for (int q = 0; q < 4; q++) acc[nt][q] = 0.0f;

#pragma unroll
    for (int ks = 0; ks < 4; ks++) {
        uint32_t ah[4], al[4];
        ldmx4(ah, sbase + F_OFF_K + ks * 2048 + offA);
        ldmx4(al, sbase + F_OFF_K + 8192 + ks * 2048 + offA);
#pragma unroll
        for (int p = 0; p < 8; p++) {
            uint32_t bf[4];
            ldmx4(bf, sbase + F_OFF_V + ks * 8192 + offB[p]);
#pragma unroll
            for (int h = 0; h < 2; h++) {
                uint32_t breg[2] = { bf[h], bf[h + 2] };
                mma16816h(acc[p * 2 + h], ah, breg);
                mma16816h(acc[p * 2 + h], al, breg);
            }
        }
    }

    {
        int r0 = wm * 16 + (lane >> 2);
        int r1 = r0 + 8;
#pragma unroll
        for (int nt = 0; nt < 16; nt++) {
            int c0 = wn * 128 + nt * 8 + (lane & 3) * 2;
            float p0 = acc[nt][0] * Uf[r0 * 260 + c0] +
                       acc[nt][2] * Uf[r1 * 260 + c0];
            float p1 = acc[nt][1] * Uf[r0 * 260 + c0 + 1] +
                       acc[nt][3] * Uf[r1 * 260 + c0 + 1];
            p0 += __shfl_xor_sync(0xffffffffu, p0, 16);
            p1 += __shfl_xor_sync(0xffffffffu, p1, 16);
            p0 += __shfl_xor_sync(0xffffffffu, p0, 8);
            p1 += __shfl_xor_sync(0xffffffffu, p1, 8);
            p0 += __shfl_xor_sync(0xffffffffu, p0, 4);
            p1 += __shfl_xor_sync(0xffffffffu, p1, 4);
            if (lane < 4) {
                atomicAdd(&outb[c0], p0);
                atomicAdd(&outb[c0 + 1], p1);
            }
        }
    }
    __syncthreads();

    int n = blockIdx.x * 256 + tid;
    if (n < N) out[n] = g_bsum[0] + outb[tid];
}

// ---------------------------------------------------------------------------
// kernel_launch
// ---------------------------------------------------------------------------
extern "C" void kernel_launch(void* const* d_in, const int* in_sizes, int n_in,
                              void* d_out, int out_size) {
    const float* sources = (const float*)d_in[0];
    const float* r       = (const float*)d_in[1];
    const float* W1      = (const float*)d_in[2];
    const float* b1      = (const float*)d_in[3];
    const float* W2      = (const float*)d_in[4];
    const float* b2      = (const float*)d_in[5];
    const float* W3      = (const float*)d_in[6];
    const float* b3      = (const float*)d_in[7];
    const float* W4      = (const float*)d_in[8];
    const float* b4      = (const float*)d_in[9];
    const float* Wb      = (const float*)d_in[10];
    const float* bb      = (const float*)d_in[11];
    float* out = (float*)d_out;

    const int S = in_sizes[0] / 4;
    const int N = in_sizes[1] / 2;

    // allow >48KB dynamic smem for the fourier kernel (idempotent host call)
    cudaFuncSetAttribute(fourier_kernel,
                         cudaFuncAttributeMaxDynamicSharedMemorySize, F_SMEM);

    // 1) fused prep: weight fp16 convert (x8) + layer1 + init
    prep_kernel<<<9217, 256>>>(sources, W1, b1, W2, W3, Wb, bb, S);

    // 2) tensor-core GELU-GEMMs (layers 2 and 3; layer-3 fuses column sum)
    {
        dim3 grid(WHID / 128, S / 128);
        mma_gemm<<<grid, 512>>>(0, b2);   // H1 -> H2 (fp16)
        mma_gemm<<<grid, 512>>>(1, b3);   // H2 -> hsum (fused column sum)
    }

    // 3) wsum = hsum @ W4^T + S*b4
    wsum_kernel<<<OUTDIM / 8, 256>>>(W4, b4, (float)S);

    // 4) fourier expansion (tensor-core bilinear form)
    fourier_kernel<<<(N + 255) / 256, 256, F_SMEM>>>(r, out, N);
}

// round 15
// speedup vs baseline: 1.2376x; 1.0196x over previous
#include <cuda_runtime.h>
#include <cuda_fp16.h>
#include <math.h>
#include <stdint.h>

// Problem constants
#define ORDER   32
#define WHID    1024
#define OUTDIM  4096
#define SMAX    2048

// ---------------------------------------------------------------------------
// Scratch (device globals -- no allocations allowed)
// ---------------------------------------------------------------------------
__device__ __half g_A[SMAX * WHID];    // H1 (fp16, gemm2 input)
__device__ __half g_C[SMAX * WHID];    // H2 (fp16, gemm3 input)
__device__ __half g_W2h[WHID * WHID];
__device__ __half g_W3h[WHID * WHID];
__device__ float g_hsum[WHID];
__device__ float g_wsum[OUTDIM];
__device__ float g_bsum[1];
__device__ float g_sink;               // write-only sink for the L2-warm CTAs

// ---------------------------------------------------------------------------
// PTX helpers
// ---------------------------------------------------------------------------
__device__ __forceinline__ uint32_t smem_u32(const void* p) {
    uint32_t a;
    asm("{ .reg .u64 t; cvta.to.shared.u64 t, %1; cvt.u32.u64 %0, t; }"
        : "=r"(a) : "l"(p));
    return a;
}
__device__ __forceinline__ void cp16(uint32_t saddr, const void* g) {
    asm volatile("cp.async.cg.shared.global [%0], [%1], 16;"
                 :: "r"(saddr), "l"(g) : "memory");
}
__device__ __forceinline__ void cp_commit() {
    asm volatile("cp.async.commit_group;" ::: "memory");
}
template <int N>
__device__ __forceinline__ void cp_wait() {
    asm volatile("cp.async.wait_group %0;" :: "n"(N) : "memory");
}
__device__ __forceinline__ void ldmx4(uint32_t* r, uint32_t addr) {
    asm volatile("ldmatrix.sync.aligned.m8n8.x4.shared.b16 {%0,%1,%2,%3}, [%4];"
                 : "=r"(r[0]), "=r"(r[1]), "=r"(r[2]), "=r"(r[3]) : "r"(addr));
}
__device__ __forceinline__ void mma16816h(float* d, const uint32_t* a,
                                          const uint32_t* b) {
    asm volatile(
        "mma.sync.aligned.m16n8k16.row.col.f32.f16.f16.f32 "
        "{%0,%1,%2,%3}, {%4,%5,%6,%7}, {%8,%9}, {%0,%1,%2,%3};"
        : "+f"(d[0]), "+f"(d[1]), "+f"(d[2]), "+f"(d[3])
        : "r"(a[0]), "r"(a[1]), "r"(a[2]), "r"(a[3]), "r"(b[0]), "r"(b[1]));
}

// ---------------------------------------------------------------------------
// GELU (tanh approximation, matches jax.nn.gelu)
// ---------------------------------------------------------------------------
__device__ __forceinline__ float gelu_f(float x) {
    const float k0 = 0.7978845608028654f;
    float x3 = x * x * x;
    float t = tanhf(k0 * (x + 0.044715f * x3));
    return 0.5f * x * (1.0f + t);
}

// ---------------------------------------------------------------------------
// prep: fused init + W2-convert (x8 vectorized) + layer1
//   blocks [0, 512)      : W2 -> fp16, 8 elems/thread
//   blocks [512, 8704)   : layer1 -> g_A fp16
//   block  8704          : zero hsum + bsum
// (W3 conversion moved to gemm0's spare CTAs)
// ---------------------------------------------------------------------------
__global__ __launch_bounds__(256)
void prep_kernel(const float* __restrict__ sources,
                 const float* __restrict__ W1, const float* __restrict__ b1,
                 const float* __restrict__ W2,
                 const float* __restrict__ Wb, const float* __restrict__ bb,
                 int S) {
    const int b = blockIdx.x;
    const int tid = threadIdx.x;

    if (b < 512) {
        int e = (b * 256 + tid) * 8;
        float4 f0 = *reinterpret_cast<const float4*>(W2 + e);
        float4 f1 = *reinterpret_cast<const float4*>(W2 + e + 4);
        __half h[8];
        h[0] = __float2half_rn(f0.x); h[1] = __float2half_rn(f0.y);
        h[2] = __float2half_rn(f0.z); h[3] = __float2half_rn(f0.w);
        h[4] = __float2half_rn(f1.x); h[5] = __float2half_rn(f1.y);
        h[6] = __float2half_rn(f1.z); h[7] = __float2half_rn(f1.w);
        *reinterpret_cast<uint4*>(g_W2h + e) = *reinterpret_cast<uint4*>(h);
    } else if (b < 8704) {
        int idx = (b - 512) * 256 + tid;
        int s = idx >> 10;
        int j = idx & (WHID - 1);
        float4 src = reinterpret_cast<const float4*>(sources)[s];
        float4 w   = reinterpret_cast<const float4*>(W1)[j];
        float acc = src.x * w.x + src.y * w.y + src.z * w.z + src.w * w.w + b1[j];
        g_A[idx] = __float2half_rn(gelu_f(acc));
    } else {
        for (int j = tid; j < WHID; j += 256) g_hsum[j] = 0.0f;
        float wb0 = Wb[0], wb1 = Wb[1], wb2 = Wb[2], wb3 = Wb[3];
        float acc = 0.0f;
        for (int s = tid; s < S; s += 256) {
            float4 v = reinterpret_cast<const float4*>(sources)[s];
            acc += v.x * wb0 + v.y * wb1 + v.z * wb2 + v.w * wb3;
        }
        __shared__ float red[256];
        red[tid] = acc;
        __syncthreads();
        for (int o = 128; o > 0; o >>= 1) {
            if (tid < o) red[tid] += red[tid + o];
            __syncthreads();
        }
        if (tid == 0) g_bsum[0] = red[0] + (float)S * bb[0];
    }
}

// ---------------------------------------------------------------------------
// mma.sync GEMM: C = gelu(A @ B^T + bias), fp16 x fp16 -> fp32 accum.
// Grid: 148 CTAs (1/SM, all wave-1 resident).
//   bid [0,128)   : GEMM tile  bm=(bid>>3)*128, bn=(bid&7)*128
//   bid [128,148) : spare-SM work:
//       stage 0 -> convert W3 (aux) -> g_W3h   (needed only by gemm1)
//       stage 1 -> stream-read W4 (aux) to warm L2 for wsum
// CTA tile 128x128, BK=32, 512 threads / 16 warps, 3-stage cp.async pipeline
// (48KB static smem). GEMM math identical to the proven R12/R14 version.
// ---------------------------------------------------------------------------
__device__ __forceinline__ uint32_t sw32(uint32_t off) {
    return off ^ ((off >> 3) & 0x10);
}

__global__ __launch_bounds__(512, 1)
void mma_gemm(int stage, const float* __restrict__ bias,
              const float* __restrict__ aux) {
    __shared__ __align__(1024) char smem[3][2][8192];

    // ---- spare-SM CTAs ----
    if (blockIdx.x >= 128) {
        int tg = (blockIdx.x - 128) * 512 + threadIdx.x;   // 0..10239
        if (stage == 0) {
            // convert W3 -> g_W3h (8 elems per chunk)
            for (int c = tg; c < (WHID * WHID) / 8; c += 20 * 512) {
                int e = c * 8;
                float4 f0 = *reinterpret_cast<const float4*>(aux + e);
                float4 f1 = *reinterpret_cast<const float4*>(aux + e + 4);
                __half h[8];
                h[0] = __float2half_rn(f0.x); h[1] = __float2half_rn(f0.y);
                h[2] = __float2half_rn(f0.z); h[3] = __float2half_rn(f0.w);
                h[4] = __float2half_rn(f1.x); h[5] = __float2half_rn(f1.y);
                h[6] = __float2half_rn(f1.z); h[7] = __float2half_rn(f1.w);
                *reinterpret_cast<uint4*>(g_W3h + e) = *reinterpret_cast<uint4*>(h);
            }
        } else {
            // warm W4 into L2 (16MB); loads kept live via data-dependent guard
            float acc = 0.0f;
            const float4* p = reinterpret_cast<const float4*>(aux);
            for (int c = tg; c < (OUTDIM * WHID) / 4; c += 20 * 512) {
                float4 v = p[c];
                acc += v.x + v.y + v.z + v.w;
            }
            if (acc == 1.0e38f) g_sink = acc;   // practically never taken
        }
        return;
    }

    const __half* A = stage ? g_C : g_A;
    const __half* B = stage ? g_W3h : g_W2h;

    const int tid = threadIdx.x;
    const int wid = tid >> 5;
    const int lane = tid & 31;
    const int bm = (blockIdx.x >> 3) * 128;
    const int bn = (blockIdx.x & 7) * 128;
    const int wm = wid & 3;
    const int wn = wid >> 2;

    const int lrow = tid >> 2;
    const int lsub = (tid >> 1) & 1;
    const int lc16 = tid & 1;
    const uint32_t loff = lsub * 4096 + sw32((uint32_t)(lrow * 32 + lc16 * 16));
    const int gk = lsub * 16 + lc16 * 8;
    const __half* srcA = A + (size_t)(bm + lrow) * WHID + gk;
    const __half* srcB = B + (size_t)(bn + lrow) * WHID + gk;

    uint32_t offA[2], offB[2];
#pragma unroll
    for (int i = 0; i < 2; i++) {
        int row = wm * 32 + i * 16 + (lane & 15);
        offA[i] = sw32((uint32_t)(row * 32 + (lane >> 4) * 16));
    }
#pragma unroll
    for (int j = 0; j < 2; j++) {
        int row = wn * 32 + j * 16 + (lane & 15);
        offB[j] = sw32((uint32_t)(row * 32 + (lane >> 4) * 16));
    }

    float acc[2][4][4];
#pragma unroll
    for (int i = 0; i < 2; i++)
#pragma unroll
        for (int j = 0; j < 4; j++)
#pragma unroll
            for (int q = 0; q < 4; q++) acc[i][j][q] = 0.0f;

#pragma unroll
    for (int p = 0; p < 2; p++) {
        cp16(smem_u32(&smem[p][0][0]) + loff, srcA + p * 32);
        cp16(smem_u32(&smem[p][1][0]) + loff, srcB + p * 32);
        cp_commit();
    }

    const int NIT = WHID / 32;   // 32
    for (int it = 0; it < NIT; it++) {
        const int st = it % 3;
        cp_wait<1>();
        __syncthreads();

        if (it + 2 < NIT) {
            const int ns = (it + 2) % 3;
            cp16(smem_u32(&smem[ns][0][0]) + loff, srcA + (it + 2) * 32);
            cp16(smem_u32(&smem[ns][1][0]) + loff, srcB + (it + 2) * 32);
        }
        cp_commit();

#pragma unroll
        for (int s = 0; s < 2; s++) {
            uint32_t ab = smem_u32(&smem[st][0][0]) + s * 4096;
            uint32_t bb = smem_u32(&smem[st][1][0]) + s * 4096;
            uint32_t a[2][4], b[2][4];
#pragma unroll
            for (int i = 0; i < 2; i++) ldmx4(a[i], ab + offA[i]);
#pragma unroll
            for (int j = 0; j < 2; j++) ldmx4(b[j], bb + offB[j]);

#pragma unroll
            for (int i = 0; i < 2; i++) {
#pragma unroll
                for (int jj = 0; jj < 4; jj++) {
                    uint32_t breg[2] = { b[jj >> 1][jj & 1], b[jj >> 1][(jj & 1) + 2] };
                    mma16816h(acc[i][jj], a[i], breg);
                }
            }
        }
    }

    // --- epilogue ---
    if (stage == 0) {
#pragma unroll
        for (int i = 0; i < 2; i++) {
            int r0 = bm + wm * 32 + i * 16 + (lane >> 2);
            int r1 = r0 + 8;
#pragma unroll
            for (int jj = 0; jj < 4; jj++) {
                int col = bn + wn * 32 + jj * 8 + (lane & 3) * 2;
                float b0 = bias[col], b1 = bias[col + 1];
                __half h0 = __float2half_rn(gelu_f(acc[i][jj][0] + b0));
                __half h1 = __float2half_rn(gelu_f(acc[i][jj][1] + b1));
                *reinterpret_cast<__half2*>(g_C + (size_t)r0 * WHID + col) =
                    __half2(h0, h1);
                h0 = __float2half_rn(gelu_f(acc[i][jj][2] + b0));
                h1 = __float2half_rn(gelu_f(acc[i][jj][3] + b1));
                *reinterpret_cast<__half2*>(g_C + (size_t)r1 * WHID + col) =
                    __half2(h0, h1);
            }
        }
    } else {
        float colacc[4][2];
#pragma unroll
        for (int jj = 0; jj < 4; jj++) { colacc[jj][0] = 0.0f; colacc[jj][1] = 0.0f; }

#pragma unroll
        for (int i = 0; i < 2; i++) {
#pragma unroll
            for (int jj = 0; jj < 4; jj++) {
                int col = bn + wn * 32 + jj * 8 + (lane & 3) * 2;
                float b0 = bias[col], b1 = bias[col + 1];
                colacc[jj][0] += gelu_f(acc[i][jj][0] + b0) + gelu_f(acc[i][jj][2] + b0);
                colacc[jj][1] += gelu_f(acc[i][jj][1] + b1) + gelu_f(acc[i][jj][3] + b1);
            }
        }
#pragma unroll
        for (int o = 16; o >= 4; o >>= 1) {
#pragma unroll
            for (int jj = 0; jj < 4; jj++) {
                colacc[jj][0] += __shfl_xor_sync(0xffffffffu, colacc[jj][0], o);
                colacc[jj][1] += __shfl_xor_sync(0xffffffffu, colacc[jj][1], o);
            }
        }
        if (lane < 4) {
#pragma unroll
            for (int jj = 0; jj < 4; jj++) {
                int col = bn + wn * 32 + jj * 8 + lane * 2;
                atomicAdd(&g_hsum[col],     colacc[jj][0]);
                atomicAdd(&g_hsum[col + 1], colacc[jj][1]);
            }
        }
    }
}

// ---------------------------------------------------------------------------
// wsum[k] = hsum . W4[k,:] + S*b4[k]  (1 row/warp, MLP~8; W4 now L2-warm)
// ---------------------------------------------------------------------------
__global__ __launch_bounds__(256)
void wsum_kernel(const float* __restrict__ W4,
                 const float* __restrict__ b4, float Sf) {
    int k = blockIdx.x * 8 + (threadIdx.x >> 5);
    int lane = threadIdx.x & 31;
    const float4* row = reinterpret_cast<const float4*>(W4 + (size_t)k * WHID);
    const float4* hs  = reinterpret_cast<const float4*>(g_hsum);

    float4 w[8], h[8];
#pragma unroll
    for (int q = 0; q < 8; q++) w[q] = row[lane + q * 32];
#pragma unroll
    for (int q = 0; q < 8; q++) h[q] = hs[lane + q * 32];

    float acc = 0.0f;
#pragma unroll
    for (int q = 0; q < 8; q++) {
        acc += w[q].x * h[q].x + w[q].y * h[q].y +
               w[q].z * h[q].z + w[q].w * h[q].w;
    }
#pragma unroll
    for (int o = 16; o > 0; o >>= 1) acc += __shfl_xor_sync(0xffffffffu, acc, o);
    if (lane == 0) g_wsum[k] = acc + Sf * b4[k];
}

// ---------------------------------------------------------------------------
// Fourier via tensor cores (proven R12 form).
// ---------------------------------------------------------------------------
#define F_OFF_K   0
#define F_OFF_V   16384
#define F_OFF_U   49152
#define F_OFF_OUT 115712
#define F_SMEM    116768

__global__ __launch_bounds__(256, 1)
void fourier_kernel(const float* __restrict__ r, float* __restrict__ out, int N) {
    extern __shared__ __align__(16) char fs[];
    const uint32_t sbase = smem_u32(fs);
    float* Uf = reinterpret_cast<float*>(fs + F_OFF_U);
    float* outb = reinterpret_cast<float*>(fs + F_OFF_OUT);

    const int tid = threadIdx.x;
    const int wid = tid >> 5;
    const int lane = tid & 31;
    const int wm = wid & 3;
    const int wn = wid >> 2;

    outb[tid] = 0.0f;

    for (int t = tid; t < 4096; t += 256) {
        int a = t >> 6, b = t & 63;
        int i = a & 31, j = b & 31;
        int c = (a < 32) ? ((b < 32) ? 0 : 2) : ((b < 32) ? 3 : 1);
        float w = g_wsum[c * 1024 + i * 32 + j];
        __half hi = __float2half_rn(w);
        __half lo = __float2half_rn(w - __half2float(hi));
        int ks = b >> 4;
        int b16 = b & 15;
        uint32_t off = ks * 2048 + sw32((uint32_t)(a * 32 + (b16 >> 3) * 16)) +
                       (b16 & 7) * 2;
        *reinterpret_cast<__half*>(fs + F_OFF_K + off) = hi;
        *reinterpret_cast<__half*>(fs + F_OFF_K + 8192 + off) = lo;
    }

    {
        int n = blockIdx.x * 256 + tid;
        float x = 0.0f, y = 0.0f;
        if (n < N) { x = r[2 * n + 0]; y = r[2 * n + 1]; }
        const float w1 = 0.6283185307179586f;   // 2*pi/10

        float sx1, cx1, sy1, cy1;
        sincosf(w1 * x, &sx1, &cx1);
        sincosf(w1 * y, &sy1, &cy1);

        float v[64], u[64];
        {
            float cc = cy1, ss = sy1;
            v[0] = cc; v[32] = ss;
#pragma unroll
            for (int k = 1; k < 32; k++) {
                float cn = cc * cy1 - ss * sy1;
                float sn = ss * cy1 + cc * sy1;
                cc = cn; ss = sn;
                v[k] = cc; v[32 + k] = ss;
            }
        }
        {
            float cc = cx1, ss = sx1;
            u[0] = cc; u[32] = ss;
#pragma unroll
            for (int k = 1; k < 32; k++) {
                float cn = cc * cx1 - ss * sx1;
                float sn = ss * cx1 + cc * sx1;
                cc = cn; ss = sn;
                u[k] = cc; u[32 + k] = ss;
            }
        }

#pragma unroll
        for (int ks = 0; ks < 4; ks++) {
#pragma unroll
            for (int c16 = 0; c16 < 2; c16++) {
                __half hv[8];
#pragma unroll
                for (int e = 0; e < 8; e++)
                    hv[e] = __float2half_rn(v[ks * 16 + c16 * 8 + e]);
                uint32_t off = F_OFF_V + ks * 8192 +
                               sw32((uint32_t)(tid * 32 + c16 * 16));
                *reinterpret_cast<uint4*>(fs + off) =
                    *reinterpret_cast<uint4*>(hv);
            }
        }
#pragma unroll
        for (int a = 0; a < 64; a++) Uf[a * 260 + tid] = u[a];
    }
    __syncthreads();

    const uint32_t offA = sw32((uint32_t)((wm * 16 + (lane & 15)) * 32 +
                                          (lane >> 4) * 16));
    uint32_t offB[8];
#pragma unroll
    for (int p = 0; p < 8; p++) {
        int row = wn * 128 + p * 16 + (lane & 15);
        offB[p] = sw32((uint32_t)(row * 32 + (lane >> 4) * 16));
    }

    float acc[16][4];
#pragma unroll
    for (int nt = 0; nt < 16; nt++)
#pragma unroll
        for (int q = 0; q < 4; q++) acc[nt][q] = 0.0f;

#pragma unroll
    for (int ks = 0; ks < 4; ks++) {
        uint32_t ah[4], al[4];
        ldmx4(ah, sbase + F_OFF_K + ks * 2048 + offA);
        ldmx4(al, sbase + F_OFF_K + 8192 + ks * 2048 + offA);
#pragma unroll
        for (int p = 0; p < 8; p++) {
            uint32_t bf[4];
            ldmx4(bf, sbase + F_OFF_V + ks * 8192 + offB[p]);
#pragma unroll
            for (int h = 0; h < 2; h++) {
                uint32_t breg[2] = { bf[h], bf[h + 2] };
                mma16816h(acc[p * 2 + h], ah, breg);
                mma16816h(acc[p * 2 + h], al, breg);
            }
        }
    }

    {
        int r0 = wm * 16 + (lane >> 2);
        int r1 = r0 + 8;
#pragma unroll
        for (int nt = 0; nt < 16; nt++) {
            int c0 = wn * 128 + nt * 8 + (lane & 3) * 2;
            float p0 = acc[nt][0] * Uf[r0 * 260 + c0] +
                       acc[nt][2] * Uf[r1 * 260 + c0];
            float p1 = acc[nt][1] * Uf[r0 * 260 + c0 + 1] +
                       acc[nt][3] * Uf[r1 * 260 + c0 + 1];
            p0 += __shfl_xor_sync(0xffffffffu, p0, 16);
            p1 += __shfl_xor_sync(0xffffffffu, p1, 16);
            p0 += __shfl_xor_sync(0xffffffffu, p0, 8);
            p1 += __shfl_xor_sync(0xffffffffu, p1, 8);
            p0 += __shfl_xor_sync(0xffffffffu, p0, 4);
            p1 += __shfl_xor_sync(0xffffffffu, p1, 4);
            if (lane < 4) {
                atomicAdd(&outb[c0], p0);
                atomicAdd(&outb[c0 + 1], p1);
            }
        }
    }
    __syncthreads();

    int n = blockIdx.x * 256 + tid;
    if (n < N) out[n] = g_bsum[0] + outb[tid];
}

// ---------------------------------------------------------------------------
// kernel_launch
// ---------------------------------------------------------------------------
extern "C" void kernel_launch(void* const* d_in, const int* in_sizes, int n_in,
                              void* d_out, int out_size) {
    const float* sources = (const float*)d_in[0];
    const float* r       = (const float*)d_in[1];
    const float* W1      = (const float*)d_in[2];
    const float* b1      = (const float*)d_in[3];
    const float* W2      = (const float*)d_in[4];
    const float* b2      = (const float*)d_in[5];
    const float* W3      = (const float*)d_in[6];
    const float* b3      = (const float*)d_in[7];
    const float* W4      = (const float*)d_in[8];
    const float* b4      = (const float*)d_in[9];
    const float* Wb      = (const float*)d_in[10];
    const float* bb      = (const float*)d_in[11];
    float* out = (float*)d_out;

    const int S = in_sizes[0] / 4;
    const int N = in_sizes[1] / 2;

    // allow >48KB dynamic smem for the fourier kernel (idempotent host call)
    cudaFuncSetAttribute(fourier_kernel,
                         cudaFuncAttributeMaxDynamicSharedMemorySize, F_SMEM);

    // 1) fused prep: W2 fp16 convert (x8) + layer1 + init
    prep_kernel<<<8705, 256>>>(sources, W1, b1, W2, Wb, bb, S);

    // 2) tensor-core GELU-GEMMs; spare CTAs: W3 convert (gemm0), W4 L2-warm (gemm1)
    mma_gemm<<<148, 512>>>(0, b2, W3);   // H1 -> H2 (fp16) + convert W3
    mma_gemm<<<148, 512>>>(1, b3, W4);   // H2 -> hsum + warm W4 in L2

    // 3) wsum = hsum @ W4^T + S*b4  (W4 L2-resident)
    wsum_kernel<<<OUTDIM / 8, 256>>>(W4, b4, (float)S);

    // 4) fourier expansion (tensor-core bilinear form)
    fourier_kernel<<<(N + 255) / 256, 256, F_SMEM>>>(r, out, N);
}